// round 1
// baseline (speedup 1.0000x reference)
#include <cuda_runtime.h>
#include <math.h>

#define Bq 2
#define Sq 2048
#define Dq 1024
#define Hq 16
#define HDq 64
#define Fq 4096
#define NTOK (Bq*Sq)   // 4096

// ---- scratch (allocation-free) ----
__device__ float g_h  [NTOK*Dq];
__device__ float g_q  [NTOK*Dq];
__device__ float g_k  [NTOK*Dq];
__device__ float g_v  [NTOK*Dq];
__device__ float g_att[NTOK*Dq];
__device__ float g_x2 [NTOK*Dq];
__device__ float g_h2 [NTOK*Dq];
__device__ float g_mlp[NTOK*Fq];

// ================= LayerNorm =================
// one block per row of D=1024, 256 threads, 4 elems/thread
__global__ void ln_kernel(const float* __restrict__ x,
                          const float* __restrict__ g,
                          const float* __restrict__ b,
                          float* __restrict__ out) {
    __shared__ float sm[32];
    int row = blockIdx.x;
    const float* xr = x + (size_t)row * Dq;
    float* outr = out + (size_t)row * Dq;
    float vals[4];
    float sum = 0.f;
#pragma unroll
    for (int i = 0; i < 4; i++) {
        vals[i] = xr[threadIdx.x + i * 256];
        sum += vals[i];
    }
    // block reduce sum
    int lane = threadIdx.x & 31, wid = threadIdx.x >> 5;
#pragma unroll
    for (int o = 16; o > 0; o >>= 1) sum += __shfl_xor_sync(0xffffffffu, sum, o);
    if (lane == 0) sm[wid] = sum;
    __syncthreads();
    float s0 = (threadIdx.x < 8) ? sm[threadIdx.x] : 0.f;
    if (wid == 0) {
#pragma unroll
        for (int o = 4; o > 0; o >>= 1) s0 += __shfl_xor_sync(0xffffffffu, s0, o);
        if (lane == 0) sm[0] = s0;
    }
    __syncthreads();
    float mu = sm[0] * (1.0f / Dq);
    __syncthreads();

    float vs = 0.f;
#pragma unroll
    for (int i = 0; i < 4; i++) {
        float d = vals[i] - mu;
        vs += d * d;
    }
#pragma unroll
    for (int o = 16; o > 0; o >>= 1) vs += __shfl_xor_sync(0xffffffffu, vs, o);
    if (lane == 0) sm[wid] = vs;
    __syncthreads();
    float v0 = (threadIdx.x < 8) ? sm[threadIdx.x] : 0.f;
    if (wid == 0) {
#pragma unroll
        for (int o = 4; o > 0; o >>= 1) v0 += __shfl_xor_sync(0xffffffffu, v0, o);
        if (lane == 0) sm[0] = v0;
    }
    __syncthreads();
    float var = sm[0] * (1.0f / Dq);
    float rstd = rsqrtf(var + 1e-5f);
#pragma unroll
    for (int i = 0; i < 4; i++) {
        int c = threadIdx.x + i * 256;
        outr[c] = (vals[i] - mu) * rstd * g[c] + b[c];
    }
}

// ================= GEMM: C[M,N] = A[M,K] @ W[N,K]^T + bias (+epilogue) =====
// EPI: 0 = none, 1 = new-gelu, 2 = add residual
template <int EPI>
__global__ void __launch_bounds__(256)
gemm_kernel(const float* __restrict__ A, const float* __restrict__ W,
            const float* __restrict__ bias, const float* __restrict__ res,
            float* __restrict__ C, int M, int Nn, int K) {
    __shared__ float As[16][128];
    __shared__ float Ws[16][128];
    int bm = blockIdx.y * 128;
    int bn = blockIdx.x * 128;
    int tid = threadIdx.x;
    int tx = tid & 15, ty = tid >> 4;
    float acc[8][8];
#pragma unroll
    for (int i = 0; i < 8; i++)
#pragma unroll
        for (int j = 0; j < 8; j++) acc[i][j] = 0.f;

    for (int k0 = 0; k0 < K; k0 += 16) {
#pragma unroll
        for (int i = 0; i < 2; i++) {
            int idx = tid * 2 + i;          // 0..511
            int r = idx >> 2;               // 0..127
            int kq = (idx & 3) * 4;         // 0,4,8,12
            float4 a = *(const float4*)(A + (size_t)(bm + r) * K + k0 + kq);
            As[kq + 0][r] = a.x; As[kq + 1][r] = a.y;
            As[kq + 2][r] = a.z; As[kq + 3][r] = a.w;
            float4 w = *(const float4*)(W + (size_t)(bn + r) * K + k0 + kq);
            Ws[kq + 0][r] = w.x; Ws[kq + 1][r] = w.y;
            Ws[kq + 2][r] = w.z; Ws[kq + 3][r] = w.w;
        }
        __syncthreads();
#pragma unroll
        for (int kk = 0; kk < 16; kk++) {
            float4 a0 = *(const float4*)&As[kk][ty * 8];
            float4 a1 = *(const float4*)&As[kk][ty * 8 + 4];
            float4 b0 = *(const float4*)&Ws[kk][tx * 8];
            float4 b1 = *(const float4*)&Ws[kk][tx * 8 + 4];
            float ar[8] = {a0.x, a0.y, a0.z, a0.w, a1.x, a1.y, a1.z, a1.w};
            float br[8] = {b0.x, b0.y, b0.z, b0.w, b1.x, b1.y, b1.z, b1.w};
#pragma unroll
            for (int i = 0; i < 8; i++)
#pragma unroll
                for (int j = 0; j < 8; j++) acc[i][j] += ar[i] * br[j];
        }
        __syncthreads();
    }

#pragma unroll
    for (int i = 0; i < 8; i++) {
        int m = bm + ty * 8 + i;
#pragma unroll
        for (int j = 0; j < 8; j++) {
            int n = bn + tx * 8 + j;
            float v = acc[i][j] + bias[n];
            if (EPI == 1) {
                float xx = v;
                v = 0.5f * xx * (1.f + tanhf(0.7978845608028654f * (xx + 0.044715f * xx * xx * xx)));
            }
            if (EPI == 2) v += res[(size_t)m * Nn + n];
            C[(size_t)m * Nn + n] = v;
        }
    }
}

// ================= Flash attention (fp32, no mask) =================
// grid: (B*H, S/128); block 128 threads; one query row per thread
__global__ void __launch_bounds__(128)
attn_kernel(const float* __restrict__ q, const float* __restrict__ k,
            const float* __restrict__ v, float* __restrict__ out) {
    __shared__ float Ks[64][HDq];
    __shared__ float Vs[64][HDq];
    int bh = blockIdx.x;
    int b = bh / Hq, h = bh % Hq;
    int qrow = blockIdx.y * 128 + threadIdx.x;
    const float* qp = q + ((size_t)(b * Sq + qrow)) * Dq + h * HDq;
    float qr[HDq];
#pragma unroll
    for (int e = 0; e < HDq; e++) qr[e] = qp[e];
    float acc[HDq];
#pragma unroll
    for (int e = 0; e < HDq; e++) acc[e] = 0.f;
    float mmax = -1e30f, lsum = 0.f;
    const float scale = 0.125f;  // 1/sqrt(64)

    for (int t = 0; t < Sq; t += 64) {
        const float* kbase = k + ((size_t)(b * Sq + t)) * Dq + h * HDq;
        const float* vbase = v + ((size_t)(b * Sq + t)) * Dq + h * HDq;
#pragma unroll
        for (int i = 0; i < 8; i++) {
            int idx = threadIdx.x + i * 128;   // float4 index 0..1023
            int r = idx >> 4;
            int c = (idx & 15) * 4;
            *(float4*)&Ks[r][c] = *(const float4*)(kbase + (size_t)r * Dq + c);
            *(float4*)&Vs[r][c] = *(const float4*)(vbase + (size_t)r * Dq + c);
        }
        __syncthreads();
        for (int j = 0; j < 64; j++) {
            float s = 0.f;
#pragma unroll
            for (int e4 = 0; e4 < 16; e4++) {
                float4 kk = *(const float4*)&Ks[j][e4 * 4];
                s += qr[e4 * 4 + 0] * kk.x + qr[e4 * 4 + 1] * kk.y +
                     qr[e4 * 4 + 2] * kk.z + qr[e4 * 4 + 3] * kk.w;
            }
            s *= scale;
            if (s > mmax) {
                float corr = __expf(mmax - s);
                lsum *= corr;
#pragma unroll
                for (int e = 0; e < HDq; e++) acc[e] *= corr;
                mmax = s;
            }
            float p = __expf(s - mmax);
            lsum += p;
#pragma unroll
            for (int e4 = 0; e4 < 16; e4++) {
                float4 vv = *(const float4*)&Vs[j][e4 * 4];
                acc[e4 * 4 + 0] += p * vv.x;
                acc[e4 * 4 + 1] += p * vv.y;
                acc[e4 * 4 + 2] += p * vv.z;
                acc[e4 * 4 + 3] += p * vv.w;
            }
        }
        __syncthreads();
    }
    float inv = 1.f / lsum;
    float* op = out + ((size_t)(b * Sq + qrow)) * Dq + h * HDq;
#pragma unroll
    for (int e = 0; e < HDq; e++) op[e] = acc[e] * inv;
}

// ================= launch =================
extern "C" void kernel_launch(void* const* d_in, const int* in_sizes, int n_in,
                              void* d_out, int out_size) {
    const float* x     = (const float*)d_in[0];
    const float* Wq    = (const float*)d_in[1];
    const float* bq    = (const float*)d_in[2];
    const float* Wk    = (const float*)d_in[3];
    const float* bk    = (const float*)d_in[4];
    const float* Wv    = (const float*)d_in[5];
    const float* bv    = (const float*)d_in[6];
    const float* Wo    = (const float*)d_in[7];
    const float* bo    = (const float*)d_in[8];
    const float* ln1_g = (const float*)d_in[9];
    const float* ln1_b = (const float*)d_in[10];
    const float* W1    = (const float*)d_in[11];
    const float* b1    = (const float*)d_in[12];
    const float* W2    = (const float*)d_in[13];
    const float* b2    = (const float*)d_in[14];
    const float* ln2_g = (const float*)d_in[15];
    const float* ln2_b = (const float*)d_in[16];
    float* out = (float*)d_out;

    float *h, *q, *k, *v, *att, *x2, *h2, *mlp;
    cudaGetSymbolAddress((void**)&h,   g_h);
    cudaGetSymbolAddress((void**)&q,   g_q);
    cudaGetSymbolAddress((void**)&k,   g_k);
    cudaGetSymbolAddress((void**)&v,   g_v);
    cudaGetSymbolAddress((void**)&att, g_att);
    cudaGetSymbolAddress((void**)&x2,  g_x2);
    cudaGetSymbolAddress((void**)&h2,  g_h2);
    cudaGetSymbolAddress((void**)&mlp, g_mlp);

    // 1) LN1
    ln_kernel<<<NTOK, 256>>>(x, ln1_g, ln1_b, h);

    // 2) QKV projections: [4096,1024] @ [1024,1024]^T
    dim3 gqkv(Dq / 128, NTOK / 128);
    gemm_kernel<0><<<gqkv, 256>>>(h, Wq, bq, nullptr, q, NTOK, Dq, Dq);
    gemm_kernel<0><<<gqkv, 256>>>(h, Wk, bk, nullptr, k, NTOK, Dq, Dq);
    gemm_kernel<0><<<gqkv, 256>>>(h, Wv, bv, nullptr, v, NTOK, Dq, Dq);

    // 3) attention
    dim3 gattn(Bq * Hq, Sq / 128);
    attn_kernel<<<gattn, 128>>>(q, k, v, att);

    // 4) output projection + residual -> x2
    gemm_kernel<2><<<gqkv, 256>>>(att, Wo, bo, x, x2, NTOK, Dq, Dq);

    // 5) LN2
    ln_kernel<<<NTOK, 256>>>(x2, ln2_g, ln2_b, h2);

    // 6) MLP up + gelu: [4096,1024] @ [4096,1024]^T -> [4096,4096]
    dim3 g1(Fq / 128, NTOK / 128);
    gemm_kernel<1><<<g1, 256>>>(h2, W1, b1, nullptr, mlp, NTOK, Fq, Dq);

    // 7) MLP down + residual -> out: [4096,4096] @ [1024,4096]^T
    dim3 g2(Dq / 128, NTOK / 128);
    gemm_kernel<2><<<g2, 256>>>(mlp, W2, b2, x2, out, NTOK, Dq, Fq);
}

// round 3
// speedup vs baseline: 1.7408x; 1.7408x over previous
#include <cuda_runtime.h>
#include <cstdint>
#include <math.h>

#define Bq 2
#define Sq 2048
#define Dq 1024
#define Hq 16
#define HDq 64
#define Fq 4096
#define NTOK (Bq*Sq)   // 4096

// ---- scratch (allocation-free) ----
__device__ float g_h  [NTOK*Dq];
__device__ float g_q  [NTOK*Dq];
__device__ float g_k  [NTOK*Dq];
__device__ float g_v  [NTOK*Dq];
__device__ float g_att[NTOK*Dq];
__device__ float g_x2 [NTOK*Dq];
__device__ float g_h2 [NTOK*Dq];
__device__ float g_mlp[NTOK*Fq];

__device__ __forceinline__ uint32_t tf32r(float x) {
    uint32_t u;
    asm("cvt.rna.tf32.f32 %0, %1;" : "=r"(u) : "f"(x));
    return u;
}

__device__ __forceinline__ void mma_tf32(float* c, const uint32_t* a, const uint32_t* b) {
    asm volatile(
        "mma.sync.aligned.m16n8k8.row.col.f32.tf32.tf32.f32 "
        "{%0,%1,%2,%3}, {%4,%5,%6,%7}, {%8,%9}, {%0,%1,%2,%3};"
        : "+f"(c[0]), "+f"(c[1]), "+f"(c[2]), "+f"(c[3])
        : "r"(a[0]), "r"(a[1]), "r"(a[2]), "r"(a[3]),
          "r"(b[0]), "r"(b[1]));
}

// ================= LayerNorm =================
__global__ void ln_kernel(const float* __restrict__ x,
                          const float* __restrict__ g,
                          const float* __restrict__ b,
                          float* __restrict__ out) {
    __shared__ float sm[32];
    int row = blockIdx.x;
    const float* xr = x + (size_t)row * Dq;
    float* outr = out + (size_t)row * Dq;
    float vals[4];
    float sum = 0.f;
#pragma unroll
    for (int i = 0; i < 4; i++) {
        vals[i] = xr[threadIdx.x + i * 256];
        sum += vals[i];
    }
    int lane = threadIdx.x & 31, wid = threadIdx.x >> 5;
#pragma unroll
    for (int o = 16; o > 0; o >>= 1) sum += __shfl_xor_sync(0xffffffffu, sum, o);
    if (lane == 0) sm[wid] = sum;
    __syncthreads();
    float s0 = (threadIdx.x < 8) ? sm[threadIdx.x] : 0.f;
    if (wid == 0) {
#pragma unroll
        for (int o = 4; o > 0; o >>= 1) s0 += __shfl_xor_sync(0xffffffffu, s0, o);
        if (lane == 0) sm[0] = s0;
    }
    __syncthreads();
    float mu = sm[0] * (1.0f / Dq);
    __syncthreads();
    float vs = 0.f;
#pragma unroll
    for (int i = 0; i < 4; i++) { float d = vals[i] - mu; vs += d * d; }
#pragma unroll
    for (int o = 16; o > 0; o >>= 1) vs += __shfl_xor_sync(0xffffffffu, vs, o);
    if (lane == 0) sm[wid] = vs;
    __syncthreads();
    float v0 = (threadIdx.x < 8) ? sm[threadIdx.x] : 0.f;
    if (wid == 0) {
#pragma unroll
        for (int o = 4; o > 0; o >>= 1) v0 += __shfl_xor_sync(0xffffffffu, v0, o);
        if (lane == 0) sm[0] = v0;
    }
    __syncthreads();
    float rstd = rsqrtf(sm[0] * (1.0f / Dq) + 1e-5f);
#pragma unroll
    for (int i = 0; i < 4; i++) {
        int c = threadIdx.x + i * 256;
        outr[c] = (vals[i] - mu) * rstd * g[c] + b[c];
    }
}

// ================= tf32 mma.sync GEMM =================
// C[M,N] = A[M,K] @ W[N,K]^T + bias (+EPI). Tile 128x128, K-chunk 32.
// 8 warps: warp_m = wid>>2 (2), warp_n = wid&3 (4). Warp tile 64x32.
// smem row stride 36 floats (conflict-free for float4 STS and frag LDS).
// EPI: 0=none, 1=new-gelu, 2=+res
#define STRIDE 36
#define STAGE_FLOATS (2 * 128 * STRIDE)   // A tile + W tile per stage

template <int EPI>
__global__ void __launch_bounds__(256, 1)
gemm_mma(const float* __restrict__ A, const float* __restrict__ W,
         const float* __restrict__ bias, const float* __restrict__ res,
         float* __restrict__ C, int M, int N, int K) {
    extern __shared__ uint32_t smem[];
    const int tid = threadIdx.x;
    const int wid = tid >> 5, lane = tid & 31;
    const int warp_m = wid >> 2, warp_n = wid & 3;
    const int bm = blockIdx.y * 128, bn = blockIdx.x * 128;

    float acc[4][4][4];
#pragma unroll
    for (int i = 0; i < 4; i++)
#pragma unroll
        for (int j = 0; j < 4; j++)
#pragma unroll
            for (int u = 0; u < 4; u++) acc[i][j][u] = 0.f;

    // per-thread global load coords: 4 float4s each for A and W per chunk
    const int lr[4] = { (tid) >> 3, (tid + 256) >> 3, (tid + 512) >> 3, (tid + 768) >> 3 };
    const int lc = (tid & 7) * 4;

    // fragment read bases (uint32 index into stage)
    const int aBase = (warp_m * 64 + (lane >> 2)) * STRIDE + (lane & 3);
    const int bBase = 128 * STRIDE + (warp_n * 32 + (lane >> 2)) * STRIDE + (lane & 3);

    float4 pa[4], pw[4];
    const int nk = K >> 5;

    // prologue: load chunk 0
    {
        const float* Ab = A + (size_t)bm * K;
        const float* Wb = W + (size_t)bn * K;
#pragma unroll
        for (int i = 0; i < 4; i++) {
            pa[i] = *(const float4*)(Ab + (size_t)(lr[i]) * K + lc);
            pw[i] = *(const float4*)(Wb + (size_t)(lr[i]) * K + lc);
        }
#pragma unroll
        for (int i = 0; i < 4; i++) {
            uint32_t* as = smem + lr[i] * STRIDE + lc;
            as[0] = tf32r(pa[i].x); as[1] = tf32r(pa[i].y);
            as[2] = tf32r(pa[i].z); as[3] = tf32r(pa[i].w);
            uint32_t* ws = smem + 128 * STRIDE + lr[i] * STRIDE + lc;
            ws[0] = tf32r(pw[i].x); ws[1] = tf32r(pw[i].y);
            ws[2] = tf32r(pw[i].z); ws[3] = tf32r(pw[i].w);
        }
    }
    __syncthreads();

    for (int kt = 0; kt < nk; kt++) {
        const uint32_t* st = smem + (kt & 1) * STAGE_FLOATS;
        // prefetch next chunk into registers
        if (kt + 1 < nk) {
            const int k0 = (kt + 1) << 5;
            const float* Ab = A + (size_t)bm * K + k0;
            const float* Wb = W + (size_t)bn * K + k0;
#pragma unroll
            for (int i = 0; i < 4; i++) {
                pa[i] = *(const float4*)(Ab + (size_t)(lr[i]) * K + lc);
                pw[i] = *(const float4*)(Wb + (size_t)(lr[i]) * K + lc);
            }
        }
        // compute on current stage: 4 k-steps of 8
#pragma unroll
        for (int ks = 0; ks < 4; ks++) {
            uint32_t af[4][4], bf[4][2];
#pragma unroll
            for (int mt = 0; mt < 4; mt++) {
                const uint32_t* p = st + aBase + mt * (16 * STRIDE) + ks * 8;
                af[mt][0] = p[0];
                af[mt][1] = p[8 * STRIDE];
                af[mt][2] = p[4];
                af[mt][3] = p[8 * STRIDE + 4];
            }
#pragma unroll
            for (int nt = 0; nt < 4; nt++) {
                const uint32_t* p = st + bBase + nt * (8 * STRIDE) + ks * 8;
                bf[nt][0] = p[0];
                bf[nt][1] = p[4];
            }
#pragma unroll
            for (int mt = 0; mt < 4; mt++)
#pragma unroll
                for (int nt = 0; nt < 4; nt++)
                    mma_tf32(acc[mt][nt], af[mt], bf[nt]);
        }
        // store prefetched chunk to the other stage
        if (kt + 1 < nk) {
            uint32_t* dst = smem + ((kt + 1) & 1) * STAGE_FLOATS;
#pragma unroll
            for (int i = 0; i < 4; i++) {
                uint32_t* as = dst + lr[i] * STRIDE + lc;
                as[0] = tf32r(pa[i].x); as[1] = tf32r(pa[i].y);
                as[2] = tf32r(pa[i].z); as[3] = tf32r(pa[i].w);
                uint32_t* ws = dst + 128 * STRIDE + lr[i] * STRIDE + lc;
                ws[0] = tf32r(pw[i].x); ws[1] = tf32r(pw[i].y);
                ws[2] = tf32r(pw[i].z); ws[3] = tf32r(pw[i].w);
            }
        }
        __syncthreads();
    }

    // epilogue
#pragma unroll
    for (int mt = 0; mt < 4; mt++) {
#pragma unroll
        for (int nt = 0; nt < 4; nt++) {
            int row = bm + warp_m * 64 + mt * 16 + (lane >> 2);
            int col = bn + warp_n * 32 + nt * 8 + 2 * (lane & 3);
#pragma unroll
            for (int half = 0; half < 2; half++) {
                int r = row + half * 8;
                float v0 = acc[mt][nt][half * 2 + 0] + bias[col];
                float v1 = acc[mt][nt][half * 2 + 1] + bias[col + 1];
                if (EPI == 1) {
                    float x0 = v0, x1 = v1;
                    v0 = 0.5f * x0 * (1.f + tanhf(0.7978845608028654f * (x0 + 0.044715f * x0 * x0 * x0)));
                    v1 = 0.5f * x1 * (1.f + tanhf(0.7978845608028654f * (x1 + 0.044715f * x1 * x1 * x1)));
                }
                if (EPI == 2) {
                    v0 += res[(size_t)r * N + col];
                    v1 += res[(size_t)r * N + col + 1];
                }
                float2 o; o.x = v0; o.y = v1;
                *(float2*)(C + (size_t)r * N + col) = o;
            }
        }
    }
}

// ================= Flash attention (fp32) =================
__global__ void __launch_bounds__(128)
attn_kernel(const float* __restrict__ q, const float* __restrict__ k,
            const float* __restrict__ v, float* __restrict__ out) {
    __shared__ float Ks[64][HDq];
    __shared__ float Vs[64][HDq];
    int bh = blockIdx.x;
    int b = bh / Hq, h = bh % Hq;
    int qrow = blockIdx.y * 128 + threadIdx.x;
    const float* qp = q + ((size_t)(b * Sq + qrow)) * Dq + h * HDq;
    float qr[HDq];
#pragma unroll
    for (int e = 0; e < HDq; e++) qr[e] = qp[e];
    float acc[HDq];
#pragma unroll
    for (int e = 0; e < HDq; e++) acc[e] = 0.f;
    float mmax = -1e30f, lsum = 0.f;
    const float scale = 0.125f;

    for (int t = 0; t < Sq; t += 64) {
        const float* kbase = k + ((size_t)(b * Sq + t)) * Dq + h * HDq;
        const float* vbase = v + ((size_t)(b * Sq + t)) * Dq + h * HDq;
#pragma unroll
        for (int i = 0; i < 8; i++) {
            int idx = threadIdx.x + i * 128;
            int r = idx >> 4;
            int c = (idx & 15) * 4;
            *(float4*)&Ks[r][c] = *(const float4*)(kbase + (size_t)r * Dq + c);
            *(float4*)&Vs[r][c] = *(const float4*)(vbase + (size_t)r * Dq + c);
        }
        __syncthreads();
        for (int j = 0; j < 64; j++) {
            float s = 0.f;
#pragma unroll
            for (int e4 = 0; e4 < 16; e4++) {
                float4 kk = *(const float4*)&Ks[j][e4 * 4];
                s += qr[e4 * 4 + 0] * kk.x + qr[e4 * 4 + 1] * kk.y +
                     qr[e4 * 4 + 2] * kk.z + qr[e4 * 4 + 3] * kk.w;
            }
            s *= scale;
            if (s > mmax) {
                float corr = __expf(mmax - s);
                lsum *= corr;
#pragma unroll
                for (int e = 0; e < HDq; e++) acc[e] *= corr;
                mmax = s;
            }
            float p = __expf(s - mmax);
            lsum += p;
#pragma unroll
            for (int e4 = 0; e4 < 16; e4++) {
                float4 vv = *(const float4*)&Vs[j][e4 * 4];
                acc[e4 * 4 + 0] += p * vv.x;
                acc[e4 * 4 + 1] += p * vv.y;
                acc[e4 * 4 + 2] += p * vv.z;
                acc[e4 * 4 + 3] += p * vv.w;
            }
        }
        __syncthreads();
    }
    float inv = 1.f / lsum;
    float* op = out + ((size_t)(b * Sq + qrow)) * Dq + h * HDq;
#pragma unroll
    for (int e = 0; e < HDq; e++) op[e] = acc[e] * inv;
}

// ================= launch =================
extern "C" void kernel_launch(void* const* d_in, const int* in_sizes, int n_in,
                              void* d_out, int out_size) {
    const float* x     = (const float*)d_in[0];
    const float* Wq    = (const float*)d_in[1];
    const float* bq    = (const float*)d_in[2];
    const float* Wk    = (const float*)d_in[3];
    const float* bk    = (const float*)d_in[4];
    const float* Wv    = (const float*)d_in[5];
    const float* bv    = (const float*)d_in[6];
    const float* Wo    = (const float*)d_in[7];
    const float* bo    = (const float*)d_in[8];
    const float* ln1_g = (const float*)d_in[9];
    const float* ln1_b = (const float*)d_in[10];
    const float* W1    = (const float*)d_in[11];
    const float* b1    = (const float*)d_in[12];
    const float* W2    = (const float*)d_in[13];
    const float* b2    = (const float*)d_in[14];
    const float* ln2_g = (const float*)d_in[15];
    const float* ln2_b = (const float*)d_in[16];
    float* out = (float*)d_out;

    float *h, *q, *k, *v, *att, *x2, *h2, *mlp;
    cudaGetSymbolAddress((void**)&h,   g_h);
    cudaGetSymbolAddress((void**)&q,   g_q);
    cudaGetSymbolAddress((void**)&k,   g_k);
    cudaGetSymbolAddress((void**)&v,   g_v);
    cudaGetSymbolAddress((void**)&att, g_att);
    cudaGetSymbolAddress((void**)&x2,  g_x2);
    cudaGetSymbolAddress((void**)&h2,  g_h2);
    cudaGetSymbolAddress((void**)&mlp, g_mlp);

    const int SMEM = 2 * STAGE_FLOATS * 4;  // 73728 bytes
    cudaFuncSetAttribute(gemm_mma<0>, cudaFuncAttributeMaxDynamicSharedMemorySize, SMEM);
    cudaFuncSetAttribute(gemm_mma<1>, cudaFuncAttributeMaxDynamicSharedMemorySize, SMEM);
    cudaFuncSetAttribute(gemm_mma<2>, cudaFuncAttributeMaxDynamicSharedMemorySize, SMEM);

    // 1) LN1
    ln_kernel<<<NTOK, 256>>>(x, ln1_g, ln1_b, h);

    // 2) QKV projections
    dim3 gqkv(Dq / 128, NTOK / 128);
    gemm_mma<0><<<gqkv, 256, SMEM>>>(h, Wq, bq, nullptr, q, NTOK, Dq, Dq);
    gemm_mma<0><<<gqkv, 256, SMEM>>>(h, Wk, bk, nullptr, k, NTOK, Dq, Dq);
    gemm_mma<0><<<gqkv, 256, SMEM>>>(h, Wv, bv, nullptr, v, NTOK, Dq, Dq);

    // 3) attention
    dim3 gattn(Bq * Hq, Sq / 128);
    attn_kernel<<<gattn, 128>>>(q, k, v, att);

    // 4) output projection + residual
    gemm_mma<2><<<gqkv, 256, SMEM>>>(att, Wo, bo, x, x2, NTOK, Dq, Dq);

    // 5) LN2
    ln_kernel<<<NTOK, 256>>>(x2, ln2_g, ln2_b, h2);

    // 6) MLP up + gelu
    dim3 g1(Fq / 128, NTOK / 128);
    gemm_mma<1><<<g1, 256, SMEM>>>(h2, W1, b1, nullptr, mlp, NTOK, Fq, Dq);

    // 7) MLP down + residual -> out
    dim3 g2(Dq / 128, NTOK / 128);
    gemm_mma<2><<<g2, 256, SMEM>>>(mlp, W2, b2, x2, out, NTOK, Dq, Fq);
}

// round 4
// speedup vs baseline: 3.3370x; 1.9169x over previous
#include <cuda_runtime.h>
#include <cstdint>
#include <math.h>

#define Bq 2
#define Sq 2048
#define Dq 1024
#define Hq 16
#define HDq 64
#define Fq 4096
#define NTOK (Bq*Sq)   // 4096

// ---- scratch (allocation-free) ----
__device__ float g_h  [NTOK*Dq];
__device__ float g_q  [NTOK*Dq];
__device__ float g_k  [NTOK*Dq];
__device__ float g_v  [NTOK*Dq];
__device__ float g_att[NTOK*Dq];
__device__ float g_x2 [NTOK*Dq];
__device__ float g_h2 [NTOK*Dq];
__device__ float g_mlp[NTOK*Fq];

__device__ __forceinline__ uint32_t tf32r(float x) {
    uint32_t u;
    asm("cvt.rna.tf32.f32 %0, %1;" : "=r"(u) : "f"(x));
    return u;
}

__device__ __forceinline__ void mma_tf32(float* c, const uint32_t* a, const uint32_t* b) {
    asm volatile(
        "mma.sync.aligned.m16n8k8.row.col.f32.tf32.tf32.f32 "
        "{%0,%1,%2,%3}, {%4,%5,%6,%7}, {%8,%9}, {%0,%1,%2,%3};"
        : "+f"(c[0]), "+f"(c[1]), "+f"(c[2]), "+f"(c[3])
        : "r"(a[0]), "r"(a[1]), "r"(a[2]), "r"(a[3]),
          "r"(b[0]), "r"(b[1]));
}

// ================= LayerNorm =================
__global__ void ln_kernel(const float* __restrict__ x,
                          const float* __restrict__ g,
                          const float* __restrict__ b,
                          float* __restrict__ out) {
    __shared__ float sm[32];
    int row = blockIdx.x;
    const float* xr = x + (size_t)row * Dq;
    float* outr = out + (size_t)row * Dq;
    float vals[4];
    float sum = 0.f;
#pragma unroll
    for (int i = 0; i < 4; i++) {
        vals[i] = xr[threadIdx.x + i * 256];
        sum += vals[i];
    }
    int lane = threadIdx.x & 31, wid = threadIdx.x >> 5;
#pragma unroll
    for (int o = 16; o > 0; o >>= 1) sum += __shfl_xor_sync(0xffffffffu, sum, o);
    if (lane == 0) sm[wid] = sum;
    __syncthreads();
    float s0 = (threadIdx.x < 8) ? sm[threadIdx.x] : 0.f;
    if (wid == 0) {
#pragma unroll
        for (int o = 4; o > 0; o >>= 1) s0 += __shfl_xor_sync(0xffffffffu, s0, o);
        if (lane == 0) sm[0] = s0;
    }
    __syncthreads();
    float mu = sm[0] * (1.0f / Dq);
    __syncthreads();
    float vs = 0.f;
#pragma unroll
    for (int i = 0; i < 4; i++) { float d = vals[i] - mu; vs += d * d; }
#pragma unroll
    for (int o = 16; o > 0; o >>= 1) vs += __shfl_xor_sync(0xffffffffu, vs, o);
    if (lane == 0) sm[wid] = vs;
    __syncthreads();
    float v0 = (threadIdx.x < 8) ? sm[threadIdx.x] : 0.f;
    if (wid == 0) {
#pragma unroll
        for (int o = 4; o > 0; o >>= 1) v0 += __shfl_xor_sync(0xffffffffu, v0, o);
        if (lane == 0) sm[0] = v0;
    }
    __syncthreads();
    float rstd = rsqrtf(sm[0] * (1.0f / Dq) + 1e-5f);
#pragma unroll
    for (int i = 0; i < 4; i++) {
        int c = threadIdx.x + i * 256;
        outr[c] = (vals[i] - mu) * rstd * g[c] + b[c];
    }
}

// ================= tf32 mma.sync GEMM =================
#define STRIDE 36
#define STAGE_FLOATS (2 * 128 * STRIDE)

template <int EPI>
__global__ void __launch_bounds__(256, 1)
gemm_mma(const float* __restrict__ A, const float* __restrict__ W,
         const float* __restrict__ bias, const float* __restrict__ res,
         float* __restrict__ C, int M, int N, int K) {
    extern __shared__ uint32_t smem[];
    const int tid = threadIdx.x;
    const int wid = tid >> 5, lane = tid & 31;
    const int warp_m = wid >> 2, warp_n = wid & 3;
    const int bm = blockIdx.y * 128, bn = blockIdx.x * 128;

    float acc[4][4][4];
#pragma unroll
    for (int i = 0; i < 4; i++)
#pragma unroll
        for (int j = 0; j < 4; j++)
#pragma unroll
            for (int u = 0; u < 4; u++) acc[i][j][u] = 0.f;

    const int lr[4] = { (tid) >> 3, (tid + 256) >> 3, (tid + 512) >> 3, (tid + 768) >> 3 };
    const int lc = (tid & 7) * 4;
    const int aBase = (warp_m * 64 + (lane >> 2)) * STRIDE + (lane & 3);
    const int bBase = 128 * STRIDE + (warp_n * 32 + (lane >> 2)) * STRIDE + (lane & 3);

    float4 pa[4], pw[4];
    const int nk = K >> 5;

    {
        const float* Ab = A + (size_t)bm * K;
        const float* Wb = W + (size_t)bn * K;
#pragma unroll
        for (int i = 0; i < 4; i++) {
            pa[i] = *(const float4*)(Ab + (size_t)(lr[i]) * K + lc);
            pw[i] = *(const float4*)(Wb + (size_t)(lr[i]) * K + lc);
        }
#pragma unroll
        for (int i = 0; i < 4; i++) {
            uint32_t* as = smem + lr[i] * STRIDE + lc;
            as[0] = tf32r(pa[i].x); as[1] = tf32r(pa[i].y);
            as[2] = tf32r(pa[i].z); as[3] = tf32r(pa[i].w);
            uint32_t* ws = smem + 128 * STRIDE + lr[i] * STRIDE + lc;
            ws[0] = tf32r(pw[i].x); ws[1] = tf32r(pw[i].y);
            ws[2] = tf32r(pw[i].z); ws[3] = tf32r(pw[i].w);
        }
    }
    __syncthreads();

    for (int kt = 0; kt < nk; kt++) {
        const uint32_t* st = smem + (kt & 1) * STAGE_FLOATS;
        if (kt + 1 < nk) {
            const int k0 = (kt + 1) << 5;
            const float* Ab = A + (size_t)bm * K + k0;
            const float* Wb = W + (size_t)bn * K + k0;
#pragma unroll
            for (int i = 0; i < 4; i++) {
                pa[i] = *(const float4*)(Ab + (size_t)(lr[i]) * K + lc);
                pw[i] = *(const float4*)(Wb + (size_t)(lr[i]) * K + lc);
            }
        }
#pragma unroll
        for (int ks = 0; ks < 4; ks++) {
            uint32_t af[4][4], bf[4][2];
#pragma unroll
            for (int mt = 0; mt < 4; mt++) {
                const uint32_t* p = st + aBase + mt * (16 * STRIDE) + ks * 8;
                af[mt][0] = p[0];
                af[mt][1] = p[8 * STRIDE];
                af[mt][2] = p[4];
                af[mt][3] = p[8 * STRIDE + 4];
            }
#pragma unroll
            for (int nt = 0; nt < 4; nt++) {
                const uint32_t* p = st + bBase + nt * (8 * STRIDE) + ks * 8;
                bf[nt][0] = p[0];
                bf[nt][1] = p[4];
            }
#pragma unroll
            for (int mt = 0; mt < 4; mt++)
#pragma unroll
                for (int nt = 0; nt < 4; nt++)
                    mma_tf32(acc[mt][nt], af[mt], bf[nt]);
        }
        if (kt + 1 < nk) {
            uint32_t* dst = smem + ((kt + 1) & 1) * STAGE_FLOATS;
#pragma unroll
            for (int i = 0; i < 4; i++) {
                uint32_t* as = dst + lr[i] * STRIDE + lc;
                as[0] = tf32r(pa[i].x); as[1] = tf32r(pa[i].y);
                as[2] = tf32r(pa[i].z); as[3] = tf32r(pa[i].w);
                uint32_t* ws = dst + 128 * STRIDE + lr[i] * STRIDE + lc;
                ws[0] = tf32r(pw[i].x); ws[1] = tf32r(pw[i].y);
                ws[2] = tf32r(pw[i].z); ws[3] = tf32r(pw[i].w);
            }
        }
        __syncthreads();
    }

#pragma unroll
    for (int mt = 0; mt < 4; mt++) {
#pragma unroll
        for (int nt = 0; nt < 4; nt++) {
            int row = bm + warp_m * 64 + mt * 16 + (lane >> 2);
            int col = bn + warp_n * 32 + nt * 8 + 2 * (lane & 3);
#pragma unroll
            for (int half = 0; half < 2; half++) {
                int r = row + half * 8;
                float v0 = acc[mt][nt][half * 2 + 0] + bias[col];
                float v1 = acc[mt][nt][half * 2 + 1] + bias[col + 1];
                if (EPI == 1) {
                    // new_gelu(x) = x * sigmoid(2*z), z = c*(x+0.044715x^3)
                    float z0 = 0.7978845608028654f * (v0 + 0.044715f * v0 * v0 * v0);
                    float z1 = 0.7978845608028654f * (v1 + 0.044715f * v1 * v1 * v1);
                    v0 = v0 / (1.f + __expf(-2.f * z0));
                    v1 = v1 / (1.f + __expf(-2.f * z1));
                }
                if (EPI == 2) {
                    v0 += res[(size_t)r * N + col];
                    v1 += res[(size_t)r * N + col + 1];
                }
                float2 o; o.x = v0; o.y = v1;
                *(float2*)(C + (size_t)r * N + col) = o;
            }
        }
    }
}

// ================= tf32 mma flash attention =================
// 256 threads = 8 warps; Q tile 128 (16 rows/warp); K/V tile 64 keys.
// smem: K[64][68] tf32, V[64][72] tf32, P[8][16][68] tf32.
#define KS_STR 68
#define VS_STR 72
#define PS_STR 68
#define ATT_SMEM ((64*KS_STR + 64*VS_STR + 8*16*PS_STR) * 4)

__global__ void __launch_bounds__(256, 1)
attn_mma(const float* __restrict__ q, const float* __restrict__ k,
         const float* __restrict__ v, float* __restrict__ out) {
    extern __shared__ uint32_t sm[];
    uint32_t* Ksm = sm;
    uint32_t* Vsm = sm + 64 * KS_STR;
    uint32_t* Psm = Vsm + 64 * VS_STR;
    const int tid = threadIdx.x, wid = tid >> 5, lane = tid & 31;
    const int g = lane >> 2, t = lane & 3;
    const int bh = blockIdx.x, b = bh >> 4, h = bh & 15;
    const int q0 = blockIdx.y * 128 + wid * 16;
    uint32_t* Pw = Psm + wid * 16 * PS_STR;

    // Q fragments (scaled by 1/sqrt(HD))
    uint32_t aq[8][4];
    const float* qb = q + ((size_t)(b * Sq + q0)) * Dq + h * HDq;
#pragma unroll
    for (int ks = 0; ks < 8; ks++) {
        aq[ks][0] = tf32r(qb[(size_t)g * Dq + ks * 8 + t] * 0.125f);
        aq[ks][1] = tf32r(qb[(size_t)(g + 8) * Dq + ks * 8 + t] * 0.125f);
        aq[ks][2] = tf32r(qb[(size_t)g * Dq + ks * 8 + t + 4] * 0.125f);
        aq[ks][3] = tf32r(qb[(size_t)(g + 8) * Dq + ks * 8 + t + 4] * 0.125f);
    }
    float o[8][4];
#pragma unroll
    for (int nt = 0; nt < 8; nt++)
#pragma unroll
        for (int u = 0; u < 4; u++) o[nt][u] = 0.f;
    float m0 = -1e30f, m1 = -1e30f, l0 = 0.f, l1 = 0.f;

    for (int kt = 0; kt < Sq / 64; kt++) {
        const float* kb = k + ((size_t)(b * Sq + kt * 64)) * Dq + h * HDq;
        const float* vb = v + ((size_t)(b * Sq + kt * 64)) * Dq + h * HDq;
#pragma unroll
        for (int i = 0; i < 4; i++) {
            int idx = tid + i * 256;
            int r = idx >> 4, c = (idx & 15) * 4;
            float4 kk = *(const float4*)(kb + (size_t)r * Dq + c);
            uint4 k4;
            k4.x = tf32r(kk.x); k4.y = tf32r(kk.y); k4.z = tf32r(kk.z); k4.w = tf32r(kk.w);
            *(uint4*)(Ksm + r * KS_STR + c) = k4;
            float4 vv = *(const float4*)(vb + (size_t)r * Dq + c);
            uint4 v4;
            v4.x = tf32r(vv.x); v4.y = tf32r(vv.y); v4.z = tf32r(vv.z); v4.w = tf32r(vv.w);
            *(uint4*)(Vsm + r * VS_STR + c) = v4;
        }
        __syncthreads();

        // S = Q K^T
        float s[8][4];
#pragma unroll
        for (int nt = 0; nt < 8; nt++)
#pragma unroll
            for (int u = 0; u < 4; u++) s[nt][u] = 0.f;
#pragma unroll
        for (int ks = 0; ks < 8; ks++) {
#pragma unroll
            for (int nt = 0; nt < 8; nt++) {
                uint32_t bf[2];
                bf[0] = Ksm[(nt * 8 + g) * KS_STR + ks * 8 + t];
                bf[1] = Ksm[(nt * 8 + g) * KS_STR + ks * 8 + t + 4];
                mma_tf32(s[nt], aq[ks], bf);
            }
        }

        // online softmax
        float mx0 = -1e30f, mx1 = -1e30f;
#pragma unroll
        for (int nt = 0; nt < 8; nt++) {
            mx0 = fmaxf(mx0, fmaxf(s[nt][0], s[nt][1]));
            mx1 = fmaxf(mx1, fmaxf(s[nt][2], s[nt][3]));
        }
        mx0 = fmaxf(mx0, __shfl_xor_sync(0xffffffffu, mx0, 1));
        mx0 = fmaxf(mx0, __shfl_xor_sync(0xffffffffu, mx0, 2));
        mx1 = fmaxf(mx1, __shfl_xor_sync(0xffffffffu, mx1, 1));
        mx1 = fmaxf(mx1, __shfl_xor_sync(0xffffffffu, mx1, 2));
        float nm0 = fmaxf(m0, mx0), nm1 = fmaxf(m1, mx1);
        float c0 = __expf(m0 - nm0), c1 = __expf(m1 - nm1);
        float sum0 = 0.f, sum1 = 0.f;
#pragma unroll
        for (int nt = 0; nt < 8; nt++) {
            s[nt][0] = __expf(s[nt][0] - nm0);
            s[nt][1] = __expf(s[nt][1] - nm0);
            s[nt][2] = __expf(s[nt][2] - nm1);
            s[nt][3] = __expf(s[nt][3] - nm1);
            sum0 += s[nt][0] + s[nt][1];
            sum1 += s[nt][2] + s[nt][3];
        }
        sum0 += __shfl_xor_sync(0xffffffffu, sum0, 1);
        sum0 += __shfl_xor_sync(0xffffffffu, sum0, 2);
        sum1 += __shfl_xor_sync(0xffffffffu, sum1, 1);
        sum1 += __shfl_xor_sync(0xffffffffu, sum1, 2);
        l0 = l0 * c0 + sum0;
        l1 = l1 * c1 + sum1;
#pragma unroll
        for (int nt = 0; nt < 8; nt++) {
            o[nt][0] *= c0; o[nt][1] *= c0;
            o[nt][2] *= c1; o[nt][3] *= c1;
        }
        m0 = nm0; m1 = nm1;

        // stage P (warp-private region)
#pragma unroll
        for (int nt = 0; nt < 8; nt++) {
            uint2 p0; p0.x = tf32r(s[nt][0]); p0.y = tf32r(s[nt][1]);
            *(uint2*)(Pw + g * PS_STR + nt * 8 + 2 * t) = p0;
            uint2 p1; p1.x = tf32r(s[nt][2]); p1.y = tf32r(s[nt][3]);
            *(uint2*)(Pw + (g + 8) * PS_STR + nt * 8 + 2 * t) = p1;
        }
        __syncwarp();

        // O += P V
#pragma unroll
        for (int ks = 0; ks < 8; ks++) {
            uint32_t ap[4];
            ap[0] = Pw[g * PS_STR + ks * 8 + t];
            ap[1] = Pw[(g + 8) * PS_STR + ks * 8 + t];
            ap[2] = Pw[g * PS_STR + ks * 8 + t + 4];
            ap[3] = Pw[(g + 8) * PS_STR + ks * 8 + t + 4];
#pragma unroll
            for (int nt = 0; nt < 8; nt++) {
                uint32_t bf[2];
                bf[0] = Vsm[(ks * 8 + t) * VS_STR + nt * 8 + g];
                bf[1] = Vsm[(ks * 8 + t + 4) * VS_STR + nt * 8 + g];
                mma_tf32(o[nt], ap, bf);
            }
        }
        __syncthreads();
    }

    float i0 = 1.f / l0, i1 = 1.f / l1;
    float* ob = out + ((size_t)(b * Sq + q0)) * Dq + h * HDq;
#pragma unroll
    for (int nt = 0; nt < 8; nt++) {
        float2 w0; w0.x = o[nt][0] * i0; w0.y = o[nt][1] * i0;
        *(float2*)(ob + (size_t)g * Dq + nt * 8 + 2 * t) = w0;
        float2 w1; w1.x = o[nt][2] * i1; w1.y = o[nt][3] * i1;
        *(float2*)(ob + (size_t)(g + 8) * Dq + nt * 8 + 2 * t) = w1;
    }
}

// ================= launch =================
extern "C" void kernel_launch(void* const* d_in, const int* in_sizes, int n_in,
                              void* d_out, int out_size) {
    const float* x     = (const float*)d_in[0];
    const float* Wq    = (const float*)d_in[1];
    const float* bq    = (const float*)d_in[2];
    const float* Wk    = (const float*)d_in[3];
    const float* bk    = (const float*)d_in[4];
    const float* Wv    = (const float*)d_in[5];
    const float* bv    = (const float*)d_in[6];
    const float* Wo    = (const float*)d_in[7];
    const float* bo    = (const float*)d_in[8];
    const float* ln1_g = (const float*)d_in[9];
    const float* ln1_b = (const float*)d_in[10];
    const float* W1    = (const float*)d_in[11];
    const float* b1    = (const float*)d_in[12];
    const float* W2    = (const float*)d_in[13];
    const float* b2    = (const float*)d_in[14];
    const float* ln2_g = (const float*)d_in[15];
    const float* ln2_b = (const float*)d_in[16];
    float* out = (float*)d_out;

    float *h, *q, *k, *v, *att, *x2, *h2, *mlp;
    cudaGetSymbolAddress((void**)&h,   g_h);
    cudaGetSymbolAddress((void**)&q,   g_q);
    cudaGetSymbolAddress((void**)&k,   g_k);
    cudaGetSymbolAddress((void**)&v,   g_v);
    cudaGetSymbolAddress((void**)&att, g_att);
    cudaGetSymbolAddress((void**)&x2,  g_x2);
    cudaGetSymbolAddress((void**)&h2,  g_h2);
    cudaGetSymbolAddress((void**)&mlp, g_mlp);

    const int SMEM = 2 * STAGE_FLOATS * 4;
    cudaFuncSetAttribute(gemm_mma<0>, cudaFuncAttributeMaxDynamicSharedMemorySize, SMEM);
    cudaFuncSetAttribute(gemm_mma<1>, cudaFuncAttributeMaxDynamicSharedMemorySize, SMEM);
    cudaFuncSetAttribute(gemm_mma<2>, cudaFuncAttributeMaxDynamicSharedMemorySize, SMEM);
    cudaFuncSetAttribute(attn_mma, cudaFuncAttributeMaxDynamicSharedMemorySize, ATT_SMEM);

    // 1) LN1
    ln_kernel<<<NTOK, 256>>>(x, ln1_g, ln1_b, h);

    // 2) QKV projections
    dim3 gqkv(Dq / 128, NTOK / 128);
    gemm_mma<0><<<gqkv, 256, SMEM>>>(h, Wq, bq, nullptr, q, NTOK, Dq, Dq);
    gemm_mma<0><<<gqkv, 256, SMEM>>>(h, Wk, bk, nullptr, k, NTOK, Dq, Dq);
    gemm_mma<0><<<gqkv, 256, SMEM>>>(h, Wv, bv, nullptr, v, NTOK, Dq, Dq);

    // 3) attention (tensor cores)
    dim3 gattn(Bq * Hq, Sq / 128);
    attn_mma<<<gattn, 256, ATT_SMEM>>>(q, k, v, att);

    // 4) output projection + residual
    gemm_mma<2><<<gqkv, 256, SMEM>>>(att, Wo, bo, x, x2, NTOK, Dq, Dq);

    // 5) LN2
    ln_kernel<<<NTOK, 256>>>(x2, ln2_g, ln2_b, h2);

    // 6) MLP up + gelu
    dim3 g1(Fq / 128, NTOK / 128);
    gemm_mma<1><<<g1, 256, SMEM>>>(h2, W1, b1, nullptr, mlp, NTOK, Fq, Dq);

    // 7) MLP down + residual -> out
    dim3 g2(Dq / 128, NTOK / 128);
    gemm_mma<2><<<g2, 256, SMEM>>>(mlp, W2, b2, x2, out, NTOK, Dq, Fq);
}

// round 5
// speedup vs baseline: 3.8047x; 1.1402x over previous
#include <cuda_runtime.h>
#include <cstdint>
#include <math.h>

#define Bq 2
#define Sq 2048
#define Dq 1024
#define Hq 16
#define HDq 64
#define Fq 4096
#define NTOK (Bq*Sq)   // 4096

// ---- scratch (allocation-free) ----
__device__ float g_h  [NTOK*Dq];
__device__ float g_q  [NTOK*Dq];
__device__ float g_k  [NTOK*Dq];
__device__ float g_v  [NTOK*Dq];
__device__ float g_att[NTOK*Dq];
__device__ float g_x2 [NTOK*Dq];
__device__ float g_h2 [NTOK*Dq];
__device__ float g_mlp[NTOK*Fq];

__device__ __forceinline__ uint32_t tf32r(float x) {
    uint32_t u;
    asm("cvt.rna.tf32.f32 %0, %1;" : "=r"(u) : "f"(x));
    return u;
}
__device__ __forceinline__ uint32_t tf32b(uint32_t xb) {
    uint32_t u;
    asm("cvt.rna.tf32.f32 %0, %1;" : "=r"(u) : "r"(xb));
    return u;
}
__device__ __forceinline__ uint32_t smem_u32(const void* p) {
    uint32_t a;
    asm("{ .reg .u64 t; cvta.to.shared.u64 t, %1; cvt.u32.u64 %0, t; }" : "=r"(a) : "l"(p));
    return a;
}
__device__ __forceinline__ void cp_async16(uint32_t dst, const void* src) {
    asm volatile("cp.async.ca.shared.global [%0], [%1], 16;" :: "r"(dst), "l"(src));
}
__device__ __forceinline__ void cp_commit() {
    asm volatile("cp.async.commit_group;" ::: "memory");
}
template <int N>
__device__ __forceinline__ void cp_wait() {
    asm volatile("cp.async.wait_group %0;" :: "n"(N) : "memory");
}

__device__ __forceinline__ void mma_tf32(float* c, const uint32_t* a, const uint32_t* b) {
    asm volatile(
        "mma.sync.aligned.m16n8k8.row.col.f32.tf32.tf32.f32 "
        "{%0,%1,%2,%3}, {%4,%5,%6,%7}, {%8,%9}, {%0,%1,%2,%3};"
        : "+f"(c[0]), "+f"(c[1]), "+f"(c[2]), "+f"(c[3])
        : "r"(a[0]), "r"(a[1]), "r"(a[2]), "r"(a[3]),
          "r"(b[0]), "r"(b[1]));
}

// ================= LayerNorm =================
__global__ void ln_kernel(const float* __restrict__ x,
                          const float* __restrict__ g,
                          const float* __restrict__ b,
                          float* __restrict__ out) {
    __shared__ float sm[32];
    int row = blockIdx.x;
    const float* xr = x + (size_t)row * Dq;
    float* outr = out + (size_t)row * Dq;
    float4 v4 = *(const float4*)(xr + threadIdx.x * 4);
    float sum = v4.x + v4.y + v4.z + v4.w;
    int lane = threadIdx.x & 31, wid = threadIdx.x >> 5;
#pragma unroll
    for (int o = 16; o > 0; o >>= 1) sum += __shfl_xor_sync(0xffffffffu, sum, o);
    if (lane == 0) sm[wid] = sum;
    __syncthreads();
    float s0 = (threadIdx.x < 8) ? sm[threadIdx.x] : 0.f;
    if (wid == 0) {
#pragma unroll
        for (int o = 4; o > 0; o >>= 1) s0 += __shfl_xor_sync(0xffffffffu, s0, o);
        if (lane == 0) sm[0] = s0;
    }
    __syncthreads();
    float mu = sm[0] * (1.0f / Dq);
    __syncthreads();
    float d0 = v4.x - mu, d1 = v4.y - mu, d2 = v4.z - mu, d3 = v4.w - mu;
    float vs = d0 * d0 + d1 * d1 + d2 * d2 + d3 * d3;
#pragma unroll
    for (int o = 16; o > 0; o >>= 1) vs += __shfl_xor_sync(0xffffffffu, vs, o);
    if (lane == 0) sm[wid] = vs;
    __syncthreads();
    float v0 = (threadIdx.x < 8) ? sm[threadIdx.x] : 0.f;
    if (wid == 0) {
#pragma unroll
        for (int o = 4; o > 0; o >>= 1) v0 += __shfl_xor_sync(0xffffffffu, v0, o);
        if (lane == 0) sm[0] = v0;
    }
    __syncthreads();
    float rstd = rsqrtf(sm[0] * (1.0f / Dq) + 1e-5f);
    int c = threadIdx.x * 4;
    float4 gg = *(const float4*)(g + c);
    float4 bb = *(const float4*)(b + c);
    float4 o;
    o.x = d0 * rstd * gg.x + bb.x;
    o.y = d1 * rstd * gg.y + bb.y;
    o.z = d2 * rstd * gg.z + bb.z;
    o.w = d3 * rstd * gg.w + bb.w;
    *(float4*)(outr + c) = o;
}

// ================= tf32 mma.sync GEMM (cp.async pipeline) =================
// C[M,N] = A[M,K] @ W[N,K]^T + bias (+EPI). Tile 128x128, K-chunk 32, 2 stages.
// 8 warps 2x4; warp tile 64x32. smem fp32, cvt->tf32 at fragment load.
#define STRIDE 36
#define STAGE_FLOATS (2 * 128 * STRIDE)   // 9216 floats / stage

template <int EPI>
__global__ void __launch_bounds__(256, 2)
gemm_mma(const float* __restrict__ A, const float* __restrict__ W,
         const float* __restrict__ bias, const float* __restrict__ res,
         float* __restrict__ C, int M, int N, int K) {
    extern __shared__ uint32_t smem[];
    const uint32_t smb = smem_u32(smem);
    const int tid = threadIdx.x;
    const int wid = tid >> 5, lane = tid & 31;
    const int warp_m = wid >> 2, warp_n = wid & 3;
    const int bm = blockIdx.y * 128, bn = blockIdx.x * 128;

    float acc[4][4][4];
#pragma unroll
    for (int i = 0; i < 4; i++)
#pragma unroll
        for (int j = 0; j < 4; j++)
#pragma unroll
            for (int u = 0; u < 4; u++) acc[i][j][u] = 0.f;

    // load map: idx = tid + i*256 -> row=idx>>3, col=(idx&7)*4
    const int lc = (tid & 7) * 4;
    const int aBase = (warp_m * 64 + (lane >> 2)) * STRIDE + (lane & 3);
    const int bBase = 128 * STRIDE + (warp_n * 32 + (lane >> 2)) * STRIDE + (lane & 3);
    const int nk = K >> 5;

    // per-stage smem dst offsets (bytes) for this thread's 8 cp.asyncs
    uint32_t dA[4], dW[4];
    const float* srcA[4];
    const float* srcW[4];
#pragma unroll
    for (int i = 0; i < 4; i++) {
        int idx = tid + i * 256;
        int r = idx >> 3;
        dA[i] = smb + (uint32_t)(r * STRIDE + lc) * 4u;
        dW[i] = smb + (uint32_t)((128 + r) * STRIDE + lc) * 4u;
        srcA[i] = A + (size_t)(bm + r) * K + lc;
        srcW[i] = W + (size_t)(bn + r) * K + lc;
    }

    // prologue: stages 0 and 1
#pragma unroll
    for (int s = 0; s < 2; s++) {
        uint32_t so = (uint32_t)(s * STAGE_FLOATS * 4);
#pragma unroll
        for (int i = 0; i < 4; i++) {
            cp_async16(dA[i] + so, srcA[i] + s * 32);
            cp_async16(dW[i] + so, srcW[i] + s * 32);
        }
        cp_commit();
    }

    for (int kt = 0; kt < nk; kt++) {
        cp_wait<1>();
        __syncthreads();
        const uint32_t* st = smem + (kt & 1) * STAGE_FLOATS;
#pragma unroll
        for (int ks = 0; ks < 4; ks++) {
            uint32_t af[4][4], bf[4][2];
#pragma unroll
            for (int mt = 0; mt < 4; mt++) {
                const uint32_t* p = st + aBase + mt * (16 * STRIDE) + ks * 8;
                af[mt][0] = tf32b(p[0]);
                af[mt][1] = tf32b(p[8 * STRIDE]);
                af[mt][2] = tf32b(p[4]);
                af[mt][3] = tf32b(p[8 * STRIDE + 4]);
            }
#pragma unroll
            for (int nt = 0; nt < 4; nt++) {
                const uint32_t* p = st + bBase + nt * (8 * STRIDE) + ks * 8;
                bf[nt][0] = tf32b(p[0]);
                bf[nt][1] = tf32b(p[4]);
            }
#pragma unroll
            for (int mt = 0; mt < 4; mt++)
#pragma unroll
                for (int nt = 0; nt < 4; nt++)
                    mma_tf32(acc[mt][nt], af[mt], bf[nt]);
        }
        __syncthreads();
        if (kt + 2 < nk) {
            uint32_t so = (uint32_t)((kt & 1) * STAGE_FLOATS * 4);
            const int koff = (kt + 2) * 32;
#pragma unroll
            for (int i = 0; i < 4; i++) {
                cp_async16(dA[i] + so, srcA[i] + koff);
                cp_async16(dW[i] + so, srcW[i] + koff);
            }
        }
        cp_commit();
    }

    // epilogue
#pragma unroll
    for (int mt = 0; mt < 4; mt++) {
#pragma unroll
        for (int nt = 0; nt < 4; nt++) {
            int row = bm + warp_m * 64 + mt * 16 + (lane >> 2);
            int col = bn + warp_n * 32 + nt * 8 + 2 * (lane & 3);
#pragma unroll
            for (int half = 0; half < 2; half++) {
                int r = row + half * 8;
                float v0 = acc[mt][nt][half * 2 + 0] + bias[col];
                float v1 = acc[mt][nt][half * 2 + 1] + bias[col + 1];
                if (EPI == 1) {
                    float z0 = 0.7978845608028654f * (v0 + 0.044715f * v0 * v0 * v0);
                    float z1 = 0.7978845608028654f * (v1 + 0.044715f * v1 * v1 * v1);
                    v0 = v0 / (1.f + __expf(-2.f * z0));
                    v1 = v1 / (1.f + __expf(-2.f * z1));
                }
                if (EPI == 2) {
                    v0 += res[(size_t)r * N + col];
                    v1 += res[(size_t)r * N + col + 1];
                }
                float2 o; o.x = v0; o.y = v1;
                *(float2*)(C + (size_t)r * N + col) = o;
            }
        }
    }
}

// ================= tf32 mma flash attention =================
#define KS_STR 68
#define VS_STR 72
#define PS_STR 68
#define ATT_SMEM ((64*KS_STR + 64*VS_STR + 8*16*PS_STR) * 4)

__global__ void __launch_bounds__(256, 1)
attn_mma(const float* __restrict__ q, const float* __restrict__ k,
         const float* __restrict__ v, float* __restrict__ out) {
    extern __shared__ uint32_t sm[];
    uint32_t* Ksm = sm;
    uint32_t* Vsm = sm + 64 * KS_STR;
    uint32_t* Psm = Vsm + 64 * VS_STR;
    const int tid = threadIdx.x, wid = tid >> 5, lane = tid & 31;
    const int g = lane >> 2, t = lane & 3;
    const int bh = blockIdx.x, b = bh >> 4, h = bh & 15;
    const int q0 = blockIdx.y * 128 + wid * 16;
    uint32_t* Pw = Psm + wid * 16 * PS_STR;

    uint32_t aq[8][4];
    const float* qb = q + ((size_t)(b * Sq + q0)) * Dq + h * HDq;
#pragma unroll
    for (int ks = 0; ks < 8; ks++) {
        aq[ks][0] = tf32r(qb[(size_t)g * Dq + ks * 8 + t] * 0.125f);
        aq[ks][1] = tf32r(qb[(size_t)(g + 8) * Dq + ks * 8 + t] * 0.125f);
        aq[ks][2] = tf32r(qb[(size_t)g * Dq + ks * 8 + t + 4] * 0.125f);
        aq[ks][3] = tf32r(qb[(size_t)(g + 8) * Dq + ks * 8 + t + 4] * 0.125f);
    }
    float o[8][4];
#pragma unroll
    for (int nt = 0; nt < 8; nt++)
#pragma unroll
        for (int u = 0; u < 4; u++) o[nt][u] = 0.f;
    float m0 = -1e30f, m1 = -1e30f, l0 = 0.f, l1 = 0.f;

    for (int kt = 0; kt < Sq / 64; kt++) {
        const float* kb = k + ((size_t)(b * Sq + kt * 64)) * Dq + h * HDq;
        const float* vb = v + ((size_t)(b * Sq + kt * 64)) * Dq + h * HDq;
#pragma unroll
        for (int i = 0; i < 4; i++) {
            int idx = tid + i * 256;
            int r = idx >> 4, c = (idx & 15) * 4;
            float4 kk = *(const float4*)(kb + (size_t)r * Dq + c);
            uint4 k4;
            k4.x = tf32r(kk.x); k4.y = tf32r(kk.y); k4.z = tf32r(kk.z); k4.w = tf32r(kk.w);
            *(uint4*)(Ksm + r * KS_STR + c) = k4;
            float4 vv = *(const float4*)(vb + (size_t)r * Dq + c);
            uint4 v4;
            v4.x = tf32r(vv.x); v4.y = tf32r(vv.y); v4.z = tf32r(vv.z); v4.w = tf32r(vv.w);
            *(uint4*)(Vsm + r * VS_STR + c) = v4;
        }
        __syncthreads();

        float s[8][4];
#pragma unroll
        for (int nt = 0; nt < 8; nt++)
#pragma unroll
            for (int u = 0; u < 4; u++) s[nt][u] = 0.f;
#pragma unroll
        for (int ks = 0; ks < 8; ks++) {
#pragma unroll
            for (int nt = 0; nt < 8; nt++) {
                uint32_t bf[2];
                bf[0] = Ksm[(nt * 8 + g) * KS_STR + ks * 8 + t];
                bf[1] = Ksm[(nt * 8 + g) * KS_STR + ks * 8 + t + 4];
                mma_tf32(s[nt], aq[ks], bf);
            }
        }

        float mx0 = -1e30f, mx1 = -1e30f;
#pragma unroll
        for (int nt = 0; nt < 8; nt++) {
            mx0 = fmaxf(mx0, fmaxf(s[nt][0], s[nt][1]));
            mx1 = fmaxf(mx1, fmaxf(s[nt][2], s[nt][3]));
        }
        mx0 = fmaxf(mx0, __shfl_xor_sync(0xffffffffu, mx0, 1));
        mx0 = fmaxf(mx0, __shfl_xor_sync(0xffffffffu, mx0, 2));
        mx1 = fmaxf(mx1, __shfl_xor_sync(0xffffffffu, mx1, 1));
        mx1 = fmaxf(mx1, __shfl_xor_sync(0xffffffffu, mx1, 2));
        float nm0 = fmaxf(m0, mx0), nm1 = fmaxf(m1, mx1);
        float c0 = __expf(m0 - nm0), c1 = __expf(m1 - nm1);
        float sum0 = 0.f, sum1 = 0.f;
#pragma unroll
        for (int nt = 0; nt < 8; nt++) {
            s[nt][0] = __expf(s[nt][0] - nm0);
            s[nt][1] = __expf(s[nt][1] - nm0);
            s[nt][2] = __expf(s[nt][2] - nm1);
            s[nt][3] = __expf(s[nt][3] - nm1);
            sum0 += s[nt][0] + s[nt][1];
            sum1 += s[nt][2] + s[nt][3];
        }
        sum0 += __shfl_xor_sync(0xffffffffu, sum0, 1);
        sum0 += __shfl_xor_sync(0xffffffffu, sum0, 2);
        sum1 += __shfl_xor_sync(0xffffffffu, sum1, 1);
        sum1 += __shfl_xor_sync(0xffffffffu, sum1, 2);
        l0 = l0 * c0 + sum0;
        l1 = l1 * c1 + sum1;
#pragma unroll
        for (int nt = 0; nt < 8; nt++) {
            o[nt][0] *= c0; o[nt][1] *= c0;
            o[nt][2] *= c1; o[nt][3] *= c1;
        }
        m0 = nm0; m1 = nm1;

#pragma unroll
        for (int nt = 0; nt < 8; nt++) {
            uint2 p0; p0.x = tf32r(s[nt][0]); p0.y = tf32r(s[nt][1]);
            *(uint2*)(Pw + g * PS_STR + nt * 8 + 2 * t) = p0;
            uint2 p1; p1.x = tf32r(s[nt][2]); p1.y = tf32r(s[nt][3]);
            *(uint2*)(Pw + (g + 8) * PS_STR + nt * 8 + 2 * t) = p1;
        }
        __syncwarp();

#pragma unroll
        for (int ks = 0; ks < 8; ks++) {
            uint32_t ap[4];
            ap[0] = Pw[g * PS_STR + ks * 8 + t];
            ap[1] = Pw[(g + 8) * PS_STR + ks * 8 + t];
            ap[2] = Pw[g * PS_STR + ks * 8 + t + 4];
            ap[3] = Pw[(g + 8) * PS_STR + ks * 8 + t + 4];
#pragma unroll
            for (int nt = 0; nt < 8; nt++) {
                uint32_t bf[2];
                bf[0] = Vsm[(ks * 8 + t) * VS_STR + nt * 8 + g];
                bf[1] = Vsm[(ks * 8 + t + 4) * VS_STR + nt * 8 + g];
                mma_tf32(o[nt], ap, bf);
            }
        }
        __syncthreads();
    }

    float i0 = 1.f / l0, i1 = 1.f / l1;
    float* ob = out + ((size_t)(b * Sq + q0)) * Dq + h * HDq;
#pragma unroll
    for (int nt = 0; nt < 8; nt++) {
        float2 w0; w0.x = o[nt][0] * i0; w0.y = o[nt][1] * i0;
        *(float2*)(ob + (size_t)g * Dq + nt * 8 + 2 * t) = w0;
        float2 w1; w1.x = o[nt][2] * i1; w1.y = o[nt][3] * i1;
        *(float2*)(ob + (size_t)(g + 8) * Dq + nt * 8 + 2 * t) = w1;
    }
}

// ================= launch =================
extern "C" void kernel_launch(void* const* d_in, const int* in_sizes, int n_in,
                              void* d_out, int out_size) {
    const float* x     = (const float*)d_in[0];
    const float* Wq    = (const float*)d_in[1];
    const float* bq    = (const float*)d_in[2];
    const float* Wk    = (const float*)d_in[3];
    const float* bk    = (const float*)d_in[4];
    const float* Wv    = (const float*)d_in[5];
    const float* bv    = (const float*)d_in[6];
    const float* Wo    = (const float*)d_in[7];
    const float* bo    = (const float*)d_in[8];
    const float* ln1_g = (const float*)d_in[9];
    const float* ln1_b = (const float*)d_in[10];
    const float* W1    = (const float*)d_in[11];
    const float* b1    = (const float*)d_in[12];
    const float* W2    = (const float*)d_in[13];
    const float* b2    = (const float*)d_in[14];
    const float* ln2_g = (const float*)d_in[15];
    const float* ln2_b = (const float*)d_in[16];
    float* out = (float*)d_out;

    float *h, *q, *k, *v, *att, *x2, *h2, *mlp;
    cudaGetSymbolAddress((void**)&h,   g_h);
    cudaGetSymbolAddress((void**)&q,   g_q);
    cudaGetSymbolAddress((void**)&k,   g_k);
    cudaGetSymbolAddress((void**)&v,   g_v);
    cudaGetSymbolAddress((void**)&att, g_att);
    cudaGetSymbolAddress((void**)&x2,  g_x2);
    cudaGetSymbolAddress((void**)&h2,  g_h2);
    cudaGetSymbolAddress((void**)&mlp, g_mlp);

    const int SMEM = 2 * STAGE_FLOATS * 4;  // 73728 B
    cudaFuncSetAttribute(gemm_mma<0>, cudaFuncAttributeMaxDynamicSharedMemorySize, SMEM);
    cudaFuncSetAttribute(gemm_mma<1>, cudaFuncAttributeMaxDynamicSharedMemorySize, SMEM);
    cudaFuncSetAttribute(gemm_mma<2>, cudaFuncAttributeMaxDynamicSharedMemorySize, SMEM);
    cudaFuncSetAttribute(attn_mma, cudaFuncAttributeMaxDynamicSharedMemorySize, ATT_SMEM);

    ln_kernel<<<NTOK, 256>>>(x, ln1_g, ln1_b, h);

    dim3 gqkv(Dq / 128, NTOK / 128);
    gemm_mma<0><<<gqkv, 256, SMEM>>>(h, Wq, bq, nullptr, q, NTOK, Dq, Dq);
    gemm_mma<0><<<gqkv, 256, SMEM>>>(h, Wk, bk, nullptr, k, NTOK, Dq, Dq);
    gemm_mma<0><<<gqkv, 256, SMEM>>>(h, Wv, bv, nullptr, v, NTOK, Dq, Dq);

    dim3 gattn(Bq * Hq, Sq / 128);
    attn_mma<<<gattn, 256, ATT_SMEM>>>(q, k, v, att);

    gemm_mma<2><<<gqkv, 256, SMEM>>>(att, Wo, bo, x, x2, NTOK, Dq, Dq);

    ln_kernel<<<NTOK, 256>>>(x2, ln2_g, ln2_b, h2);

    dim3 g1(Fq / 128, NTOK / 128);
    gemm_mma<1><<<g1, 256, SMEM>>>(h2, W1, b1, nullptr, mlp, NTOK, Fq, Dq);

    dim3 g2(Dq / 128, NTOK / 128);
    gemm_mma<2><<<g2, 256, SMEM>>>(mlp, W2, b2, x2, out, NTOK, Dq, Fq);
}